// round 5
// baseline (speedup 1.0000x reference)
#include <cuda_runtime.h>
#include <cstdint>

#define BB 16
#define CC 128
#define HEAD 8
#define DKK 16
#define NNN 2500
#define LLL 12
#define NPOS (NNN*LLL)
#define TP 128
#define NT ((NPOS + TP - 1)/TP)      /* 235 */
#define NTILES (NT*BB)               /* 3760 */
#define GRID_PERS 152
#define VS_PITCH 136

// ---------------- device scratch ----------------
__device__ __align__(16) float4 g_WFH[3*4096];   // weight fragments hi: [w][strip][s][lane]
__device__ __align__(16) float4 g_WFL[3*4096];   // weight fragments lo
__device__ __align__(16) float g_key[HEAD*LLL*NNN*DKK];
__device__ __align__(16) float g_kv[BB*LLL*HEAD*DKK*DKK];
__device__ __align__(16) float g_q[(size_t)BB*NPOS*CC];   // [b][p][c] natural
__device__ __align__(16) float g_o[(size_t)BB*NPOS*CC];   // [b][p][c] PERMUTED within 8-blocks

// ---------------- helpers ----------------
__device__ __forceinline__ float cvt_tf32(float x) {
    uint32_t r;
    asm("cvt.rna.tf32.f32 %0, %1;" : "=r"(r) : "f"(x));
    return __uint_as_float(r);
}
__device__ __forceinline__ void mma8(float d[4], const uint32_t a[4], uint32_t b0, uint32_t b1) {
    asm volatile("mma.sync.aligned.m16n8k8.row.col.f32.tf32.tf32.f32 "
        "{%0,%1,%2,%3}, {%4,%5,%6,%7}, {%8,%9}, {%0,%1,%2,%3};"
        : "+f"(d[0]), "+f"(d[1]), "+f"(d[2]), "+f"(d[3])
        : "r"(a[0]), "r"(a[1]), "r"(a[2]), "r"(a[3]), "r"(b0), "r"(b1));
}

// ---------------- prep: weight fragments ----------------
__global__ void k_prep_w(const float* __restrict__ Wq, const float* __restrict__ Wv,
                         const float* __restrict__ Wc) {
    int w = blockIdx.x;
    const float* src = (w == 0) ? Wq : (w == 1) ? Wv : Wc;
    for (int f = threadIdx.x; f < 4096; f += 256) {
        int strip = f >> 9, s = (f >> 5) & 15, lane = f & 31;
        int g = lane >> 2, t = lane & 3;
        int m0 = strip * 16 + g, m1 = m0 + 8;
        int k0 = s * 8 + t, k1 = k0 + 4;
        float a0 = src[m0*128 + k0], a1 = src[m1*128 + k0];
        float a2 = src[m0*128 + k1], a3 = src[m1*128 + k1];
        float h0 = cvt_tf32(a0), h1 = cvt_tf32(a1), h2 = cvt_tf32(a2), h3 = cvt_tf32(a3);
        g_WFH[w*4096 + f] = make_float4(h0, h1, h2, h3);
        g_WFL[w*4096 + f] = make_float4(cvt_tf32(a0 - h0), cvt_tf32(a1 - h1),
                                        cvt_tf32(a2 - h2), cvt_tf32(a3 - h3));
    }
}

__global__ void k_key(const float* __restrict__ s_bank) {
    int r = blockIdx.x * 256 + threadIdx.x;
    if (r >= HEAD*LLL*NNN) return;
    const float4* src = (const float4*)(s_bank + (size_t)r * 16);
    float4 v0 = src[0], v1 = src[1], v2 = src[2], v3 = src[3];
    float v[16] = {v0.x,v0.y,v0.z,v0.w, v1.x,v1.y,v1.z,v1.w,
                   v2.x,v2.y,v2.z,v2.w, v3.x,v3.y,v3.z,v3.w};
    float mx = v[0];
#pragma unroll
    for (int i = 1; i < 16; i++) mx = fmaxf(mx, v[i]);
    float s = 0.f;
#pragma unroll
    for (int i = 0; i < 16; i++) { v[i] = __expf(0.25f * (v[i] - mx)); s += v[i]; }
    float inv = 1.f / s;
#pragma unroll
    for (int i = 0; i < 16; i++) v[i] *= inv;
    float4* dst = (float4*)(g_key + (size_t)r * 16);
    dst[0] = make_float4(v[0],v[1],v[2],v[3]);
    dst[1] = make_float4(v[4],v[5],v[6],v[7]);
    dst[2] = make_float4(v[8],v[9],v[10],v[11]);
    dst[3] = make_float4(v[12],v[13],v[14],v[15]);
}

__global__ void k_zero_kv() {
    int i = blockIdx.x * 256 + threadIdx.x;
    ((float4*)g_kv)[i] = make_float4(0.f, 0.f, 0.f, 0.f);
}

// ---------------- staging: activations -> fragment-major smem ----------------
// unit u: lane=u&31, ks=(u>>5)&15, nt=u>>9; holds {bh(k0),bl(k0),bh(k1),bl(k1)}
// for k0=ks*8+(lane&3), k1=k0+4, n = nt*8+(lane>>2).
__device__ __forceinline__ void stage_x(const float* __restrict__ xb, int pc, int tid,
                                        float4* frag) {
    for (int u = tid; u < 8192; u += 256) {
        int lane = u & 31, ks = (u >> 5) & 15, nt = u >> 9;
        int p = nt * 8 + (lane >> 2);
        int c = ks * 8 + (lane & 3);
        float v0 = 0.f, v1 = 0.f;
        if (p < pc) {
            v0 = __ldg(xb + (size_t)c * NPOS + p);
            v1 = __ldg(xb + (size_t)(c + 4) * NPOS + p);
        }
        float h0 = cvt_tf32(v0), h1 = cvt_tf32(v1);
        frag[u] = make_float4(h0, cvt_tf32(v0 - h0), h1, cvt_tf32(v1 - h1));
    }
}
// o source: [p][c] with channels permuted so (c, c+4) adjacent: float2 at p*64 + ks*4 + t
__device__ __forceinline__ void stage_o(const float* __restrict__ ob, int pc, int tid,
                                        float4* frag) {
    const float2* ob2 = (const float2*)ob;
    for (int u = tid; u < 8192; u += 256) {
        int lane = u & 31, ks = (u >> 5) & 15, nt = u >> 9;
        int p = nt * 8 + (lane >> 2);
        int t = lane & 3;
        float2 r = make_float2(0.f, 0.f);
        if (p < pc) r = __ldg(ob2 + (size_t)p * 64 + ks * 4 + t);
        float h0 = cvt_tf32(r.x), h1 = cvt_tf32(r.y);
        frag[u] = make_float4(h0, cvt_tf32(r.x - h0), h1, cvt_tf32(r.y - h1));
    }
}

// load A fragments for weight w into registers
__device__ __forceinline__ void load_afrag(int w, int wid, int lane,
                                           uint32_t aH[16][4], uint32_t aL[16][4]) {
    const float4* PH = g_WFH + w*4096 + wid*512 + lane;
    const float4* PL = g_WFL + w*4096 + wid*512 + lane;
#pragma unroll
    for (int s = 0; s < 16; s++) {
        float4 h = __ldg(PH + s*32);
        float4 l = __ldg(PL + s*32);
        aH[s][0] = __float_as_uint(h.x); aH[s][1] = __float_as_uint(h.y);
        aH[s][2] = __float_as_uint(h.z); aH[s][3] = __float_as_uint(h.w);
        aL[s][0] = __float_as_uint(l.x); aL[s][1] = __float_as_uint(l.y);
        aL[s][2] = __float_as_uint(l.z); aL[s][3] = __float_as_uint(l.w);
    }
}

// 3-term tf32 GEMM for one pair of n-tiles
__device__ __forceinline__ void gemm_pair(const float4* frag, int nt0, int lane,
                                          const uint32_t aH[16][4], const uint32_t aL[16][4],
                                          float d0[4], float d1[4]) {
#pragma unroll
    for (int i = 0; i < 4; i++) { d0[i] = 0.f; d1[i] = 0.f; }
    const float4* fb0 = frag + nt0*512 + lane;
    const float4* fb1 = fb0 + 512;
#pragma unroll
    for (int s = 0; s < 16; s++) {
        float4 u0 = fb0[s*32];
        float4 u1 = fb1[s*32];
        uint32_t u0hx = __float_as_uint(u0.x), u0lx = __float_as_uint(u0.y);
        uint32_t u0hz = __float_as_uint(u0.z), u0lz = __float_as_uint(u0.w);
        uint32_t u1hx = __float_as_uint(u1.x), u1lx = __float_as_uint(u1.y);
        uint32_t u1hz = __float_as_uint(u1.z), u1lz = __float_as_uint(u1.w);
        mma8(d0, aH[s], u0hx, u0hz);
        mma8(d1, aH[s], u1hx, u1hz);
        mma8(d0, aL[s], u0hx, u0hz);
        mma8(d1, aL[s], u1hx, u1hz);
        mma8(d0, aH[s], u0lx, u0lz);
        mma8(d1, aH[s], u1lx, u1lz);
    }
}

// =======================================================================
// kernelQV: q = softmax(relu(Wq x+bq)) -> g_q[b][p][c]; v = relu(Wv x+bv);
//           kv[b,l,h] += key^T v
// =======================================================================
#define SMEM_QV_BYTES (8192*16 + VS_PITCH*128*4)
__global__ void __launch_bounds__(256, 1)
kernelQV(const float* __restrict__ x, const float* __restrict__ bq,
         const float* __restrict__ bv) {
    extern __shared__ float4 frag[];
    float* vsm = (float*)(frag + 8192);

    int tid = threadIdx.x, wid = tid >> 5, lane = tid & 31;
    int g = lane >> 2, t = lane & 3;
    int r0 = wid * 16 + g, r1 = r0 + 8;

    uint32_t aH[16][4], aL[16][4];
    float bq0 = __ldg(bq + r0), bq1 = __ldg(bq + r1);
    float bv0 = __ldg(bv + r0), bv1 = __ldg(bv + r1);
    int xk = lane & 15, yb = (lane >> 4) * 8;

    for (int tt = blockIdx.x; tt < NTILES; tt += gridDim.x) {
        int b = tt / NT, p0 = (tt % NT) * TP;
        int pc = min(TP, NPOS - p0);

        stage_x(x + ((size_t)b * CC) * NPOS + p0, pc, tid, frag);
        __syncthreads();

        // ---- phase Q ----
        load_afrag(0, wid, lane, aH, aL);
        float* qb = g_q + ((size_t)b * NPOS + p0) * CC;
#pragma unroll 1
        for (int nt2 = 0; nt2 < 8; nt2++) {
            float d0[4], d1[4];
            gemm_pair(frag, nt2*2, lane, aH, aL, d0, d1);
#pragma unroll
            for (int half = 0; half < 2; half++) {
                float* d = half ? d1 : d0;
                int col0 = (nt2*2 + half) * 8 + 2*t;
                float v0 = fmaxf(d[0] + bq0, 0.f);
                float v1 = fmaxf(d[1] + bq0, 0.f);
                float v2 = fmaxf(d[2] + bq1, 0.f);
                float v3 = fmaxf(d[3] + bq1, 0.f);
                float m0 = fmaxf(v0, v2), m1 = fmaxf(v1, v3);
#pragma unroll
                for (int o = 4; o < 32; o <<= 1) {
                    m0 = fmaxf(m0, __shfl_xor_sync(0xffffffffu, m0, o));
                    m1 = fmaxf(m1, __shfl_xor_sync(0xffffffffu, m1, o));
                }
                float e0 = __expf(0.25f*(v0 - m0)), e2 = __expf(0.25f*(v2 - m0));
                float e1 = __expf(0.25f*(v1 - m1)), e3 = __expf(0.25f*(v3 - m1));
                float s0 = e0 + e2, s1 = e1 + e3;
#pragma unroll
                for (int o = 4; o < 32; o <<= 1) {
                    s0 += __shfl_xor_sync(0xffffffffu, s0, o);
                    s1 += __shfl_xor_sync(0xffffffffu, s1, o);
                }
                float i0 = 1.f / s0, i1 = 1.f / s1;
                if (col0 < pc) {
                    qb[(size_t)col0 * CC + r0] = e0 * i0;
                    qb[(size_t)col0 * CC + r1] = e2 * i0;
                }
                if (col0 + 1 < pc) {
                    qb[(size_t)(col0+1) * CC + r0] = e1 * i1;
                    qb[(size_t)(col0+1) * CC + r1] = e3 * i1;
                }
            }
        }

        // ---- phase V ----
        load_afrag(1, wid, lane, aH, aL);
#pragma unroll 1
        for (int nt2 = 0; nt2 < 8; nt2++) {
            float d0[4], d1[4];
            gemm_pair(frag, nt2*2, lane, aH, aL, d0, d1);
#pragma unroll
            for (int half = 0; half < 2; half++) {
                float* d = half ? d1 : d0;
                int col0 = (nt2*2 + half) * 8 + 2*t;
                *(float2*)(vsm + r0 * VS_PITCH + col0) =
                    make_float2(fmaxf(d[0] + bv0, 0.f), fmaxf(d[1] + bv0, 0.f));
                *(float2*)(vsm + r1 * VS_PITCH + col0) =
                    make_float2(fmaxf(d[2] + bv1, 0.f), fmaxf(d[3] + bv1, 0.f));
            }
        }
        __syncthreads();

        // ---- kv accumulation: warp = head ----
        {
            int h = wid;
            const float* keyh = g_key + (size_t)h * (LLL * NNN * DKK);
            for (int l = 0; l < LLL; l++) {
                float a8[8];
#pragma unroll
                for (int j = 0; j < 8; j++) a8[j] = 0.f;
                int s = ((l - p0) % 12 + 12) % 12;
                for (int pp = s; pp < pc; pp += 12) {
                    int n = (p0 + pp) / 12;
                    float kx = __ldg(&keyh[((size_t)l * NNN + n) * DKK + xk]);
                    const float* vb = vsm + (h * 16 + yb) * VS_PITCH + pp;
#pragma unroll
                    for (int j = 0; j < 8; j++) a8[j] = fmaf(kx, vb[j * VS_PITCH], a8[j]);
                }
                float* kvp = g_kv + ((((size_t)b * LLL + l) * HEAD + h) * DKK + xk) * DKK + yb;
#pragma unroll
                for (int j = 0; j < 8; j++) atomicAdd(kvp + j, a8[j]);
            }
        }
        __syncthreads();
    }
}

// =======================================================================
// kernelB1: o[b,p,:] = q[b,p,:] @ kv[b,l(p)]  (writes PERMUTED channel blocks)
// =======================================================================
__global__ void __launch_bounds__(256, 4)
kernelB1() {
    __shared__ float kvs[HEAD*DKK*DKK];
    int b = blockIdx.z, l = blockIdx.y;
    int tid = threadIdx.x;

    const float* kvb = g_kv + ((size_t)b * LLL + l) * (HEAD * DKK * DKK);
    for (int i = tid; i < HEAD*DKK*DKK; i += 256) kvs[i] = kvb[i];
    __syncthreads();

    int n = blockIdx.x * 256 + tid;
    if (n >= NNN) return;
    int P = n * 12 + l;
    const float* qr = g_q + ((size_t)b * NPOS + P) * CC;
    float* orow = g_o + ((size_t)b * NPOS + P) * CC;

#pragma unroll
    for (int h = 0; h < HEAD; h++) {
        const float4* q4 = (const float4*)(qr + h * 16);
        float4 a0 = q4[0], a1 = q4[1], a2 = q4[2], a3 = q4[3];
        float q16[16] = {a0.x,a0.y,a0.z,a0.w, a1.x,a1.y,a1.z,a1.w,
                         a2.x,a2.y,a2.z,a2.w, a3.x,a3.y,a3.z,a3.w};
        float o16[16];
#pragma unroll
        for (int y = 0; y < 16; y++) o16[y] = 0.f;
        const float* kvh = kvs + h * 256;
#pragma unroll
        for (int xq = 0; xq < 16; xq++) {
            float qv = q16[xq];
            const float4* kr = (const float4*)(kvh + xq * 16);
            float4 k0 = kr[0], k1 = kr[1], k2 = kr[2], k3 = kr[3];
            o16[0]  = fmaf(qv, k0.x, o16[0]);  o16[1]  = fmaf(qv, k0.y, o16[1]);
            o16[2]  = fmaf(qv, k0.z, o16[2]);  o16[3]  = fmaf(qv, k0.w, o16[3]);
            o16[4]  = fmaf(qv, k1.x, o16[4]);  o16[5]  = fmaf(qv, k1.y, o16[5]);
            o16[6]  = fmaf(qv, k1.z, o16[6]);  o16[7]  = fmaf(qv, k1.w, o16[7]);
            o16[8]  = fmaf(qv, k2.x, o16[8]);  o16[9]  = fmaf(qv, k2.y, o16[9]);
            o16[10] = fmaf(qv, k2.z, o16[10]); o16[11] = fmaf(qv, k2.w, o16[11]);
            o16[12] = fmaf(qv, k3.x, o16[12]); o16[13] = fmaf(qv, k3.y, o16[13]);
            o16[14] = fmaf(qv, k3.z, o16[14]); o16[15] = fmaf(qv, k3.w, o16[15]);
        }
        // permuted within each 8-block: slots {c0,c4,c1,c5,c2,c6,c3,c7}
        float4* od = (float4*)(orow + h * 16);
        od[0] = make_float4(o16[0],  o16[4],  o16[1],  o16[5]);
        od[1] = make_float4(o16[2],  o16[6],  o16[3],  o16[7]);
        od[2] = make_float4(o16[8],  o16[12], o16[9],  o16[13]);
        od[3] = make_float4(o16[10], o16[14], o16[11], o16[15]);
    }
}

// =======================================================================
// kernelB2: out = relu(Wc o + bc) -> out[b][c][p]
// =======================================================================
#define SMEM_B2_BYTES (8192*16)
__global__ void __launch_bounds__(256, 1)
kernelB2(const float* __restrict__ bc, float* __restrict__ out) {
    extern __shared__ float4 frag[];

    int tid = threadIdx.x, wid = tid >> 5, lane = tid & 31;
    int g = lane >> 2, t = lane & 3;
    int r0 = wid * 16 + g, r1 = r0 + 8;

    uint32_t aH[16][4], aL[16][4];
    load_afrag(2, wid, lane, aH, aL);
    float bc0 = __ldg(bc + r0), bc1 = __ldg(bc + r1);

    for (int tt = blockIdx.x; tt < NTILES; tt += gridDim.x) {
        int b = tt / NT, p0 = (tt % NT) * TP;
        int pc = min(TP, NPOS - p0);

        stage_o(g_o + ((size_t)b * NPOS + p0) * CC, pc, tid, frag);
        __syncthreads();

        float* ob = out + (size_t)b * CC * NPOS + p0;
#pragma unroll 1
        for (int nt2 = 0; nt2 < 8; nt2++) {
            float d0[4], d1[4];
            gemm_pair(frag, nt2*2, lane, aH, aL, d0, d1);
#pragma unroll
            for (int half = 0; half < 2; half++) {
                float* d = half ? d1 : d0;
                int col0 = (nt2*2 + half) * 8 + 2*t;
                if (col0 < pc) {
                    *(float2*)(ob + (size_t)r0 * NPOS + col0) =
                        make_float2(fmaxf(d[0] + bc0, 0.f), fmaxf(d[1] + bc0, 0.f));
                    *(float2*)(ob + (size_t)r1 * NPOS + col0) =
                        make_float2(fmaxf(d[2] + bc1, 0.f), fmaxf(d[3] + bc1, 0.f));
                }
            }
        }
        __syncthreads();
    }
}

// ---------------- launch ----------------
extern "C" void kernel_launch(void* const* d_in, const int* in_sizes, int n_in,
                              void* d_out, int out_size) {
    (void)in_sizes; (void)n_in; (void)out_size;
    const float* x      = (const float*)d_in[0];
    const float* Wq     = (const float*)d_in[1];
    const float* bq     = (const float*)d_in[2];
    const float* Wv     = (const float*)d_in[3];
    const float* bv     = (const float*)d_in[4];
    const float* Wc     = (const float*)d_in[5];
    const float* bc     = (const float*)d_in[6];
    const float* s_bank = (const float*)d_in[7];
    float* out = (float*)d_out;

    cudaFuncSetAttribute(kernelQV, cudaFuncAttributeMaxDynamicSharedMemorySize, SMEM_QV_BYTES);
    cudaFuncSetAttribute(kernelB2, cudaFuncAttributeMaxDynamicSharedMemorySize, SMEM_B2_BYTES);

    k_prep_w<<<3, 256>>>(Wq, Wv, Wc);
    k_key<<<(HEAD*LLL*NNN + 255) / 256, 256>>>(s_bank);
    k_zero_kv<<<(BB*LLL*HEAD*DKK*DKK/4) / 256, 256>>>();
    kernelQV<<<GRID_PERS, 256, SMEM_QV_BYTES>>>(x, bq, bv);
    kernelB1<<<dim3((NNN + 255) / 256, LLL, BB), 256>>>();
    kernelB2<<<GRID_PERS, 256, SMEM_B2_BYTES>>>(bc, out);
}

// round 6
// speedup vs baseline: 1.2990x; 1.2990x over previous
#include <cuda_runtime.h>
#include <cuda_bf16.h>
#include <cstdint>

#define BB 16
#define CC 128
#define HEAD 8
#define DKK 16
#define NNN 2500
#define LLL 12
#define NPOS (NNN*LLL)
#define TP 128
#define NT ((NPOS + TP - 1)/TP)      /* 235 */
#define NTILES (NT*BB)               /* 3760 */
#define GRID_PERS 152
#define VSP 129

// ---------------- device scratch ----------------
__device__ __align__(16) uint4 g_WFH[3*2048];   // bf16 A-frags hi: [w][mg][strip][chunk][lane]
__device__ __align__(16) uint4 g_WFL[3*2048];   // bf16 A-frags lo
__device__ __align__(16) float g_key[HEAD*LLL*NNN*DKK];
__device__ __align__(16) float g_kv[BB*LLL*HEAD*DKK*DKK];
__device__ __align__(16) float g_q[(size_t)BB*NPOS*CC];   // [b][p][c]
__device__ __align__(16) float g_o[(size_t)BB*NPOS*CC];   // [b][p][c]

// ---------------- helpers ----------------
__device__ __forceinline__ float rbf(float x) {
    return __bfloat162float(__float2bfloat16(x));
}
// pack two floats to bf16x2: low half = vlo, high half = vhi
__device__ __forceinline__ uint32_t packbf(float vlo, float vhi) {
    uint32_t r;
    asm("cvt.rn.bf16x2.f32 %0, %1, %2;" : "=r"(r) : "f"(vhi), "f"(vlo));
    return r;
}
__device__ __forceinline__ void mma16(float d[4], const uint32_t a[4], uint32_t b0, uint32_t b1) {
    asm volatile("mma.sync.aligned.m16n8k16.row.col.f32.bf16.bf16.f32 "
        "{%0,%1,%2,%3}, {%4,%5,%6,%7}, {%8,%9}, {%0,%1,%2,%3};"
        : "+f"(d[0]), "+f"(d[1]), "+f"(d[2]), "+f"(d[3])
        : "r"(a[0]), "r"(a[1]), "r"(a[2]), "r"(a[3]), "r"(b0), "r"(b1));
}

// ---------------- prep: weight A-fragments (bf16 hi/lo) ----------------
// unit f: lane=f&31, chunk=(f>>5)&7, strip=(f>>8)&1, mg=f>>9
// A[m][k]=W[m][k]; a0={W[m0][k0],W[m0][k0+1]}, a1=rows m0+8, a2=cols k0+8, a3=both
__global__ void k_prep_w(const float* __restrict__ Wq, const float* __restrict__ Wv,
                         const float* __restrict__ Wc) {
    int w = blockIdx.x;
    const float* src = (w == 0) ? Wq : (w == 1) ? Wv : Wc;
    for (int f = threadIdx.x; f < 2048; f += 256) {
        int lane = f & 31, chunk = (f >> 5) & 7, strip = (f >> 8) & 1, mg = f >> 9;
        int g = lane >> 2, t = lane & 3;
        int m0 = mg * 32 + strip * 16 + g, m1 = m0 + 8;
        int k0 = chunk * 16 + 2 * t;
        float w00 = src[m0*128 + k0],     w01 = src[m0*128 + k0 + 1];
        float w10 = src[m1*128 + k0],     w11 = src[m1*128 + k0 + 1];
        float w02 = src[m0*128 + k0 + 8], w03 = src[m0*128 + k0 + 9];
        float w12 = src[m1*128 + k0 + 8], w13 = src[m1*128 + k0 + 9];
        uint4 H, L;
        H.x = packbf(w00, w01); H.y = packbf(w10, w11);
        H.z = packbf(w02, w03); H.w = packbf(w12, w13);
        L.x = packbf(w00 - rbf(w00), w01 - rbf(w01));
        L.y = packbf(w10 - rbf(w10), w11 - rbf(w11));
        L.z = packbf(w02 - rbf(w02), w03 - rbf(w03));
        L.w = packbf(w12 - rbf(w12), w13 - rbf(w13));
        g_WFH[w*2048 + f] = H;
        g_WFL[w*2048 + f] = L;
    }
}

__global__ void k_key(const float* __restrict__ s_bank) {
    int r = blockIdx.x * 256 + threadIdx.x;
    if (r >= HEAD*LLL*NNN) return;
    const float4* src = (const float4*)(s_bank + (size_t)r * 16);
    float4 v0 = src[0], v1 = src[1], v2 = src[2], v3 = src[3];
    float v[16] = {v0.x,v0.y,v0.z,v0.w, v1.x,v1.y,v1.z,v1.w,
                   v2.x,v2.y,v2.z,v2.w, v3.x,v3.y,v3.z,v3.w};
    float mx = v[0];
#pragma unroll
    for (int i = 1; i < 16; i++) mx = fmaxf(mx, v[i]);
    float s = 0.f;
#pragma unroll
    for (int i = 0; i < 16; i++) { v[i] = __expf(0.25f * (v[i] - mx)); s += v[i]; }
    float inv = 1.f / s;
#pragma unroll
    for (int i = 0; i < 16; i++) v[i] *= inv;
    float4* dst = (float4*)(g_key + (size_t)r * 16);
    dst[0] = make_float4(v[0],v[1],v[2],v[3]);
    dst[1] = make_float4(v[4],v[5],v[6],v[7]);
    dst[2] = make_float4(v[8],v[9],v[10],v[11]);
    dst[3] = make_float4(v[12],v[13],v[14],v[15]);
}

__global__ void k_zero_kv() {
    int i = blockIdx.x * 256 + threadIdx.x;
    ((float4*)g_kv)[i] = make_float4(0.f, 0.f, 0.f, 0.f);
}

// ---------------- staging: B-fragments, frag[nt(16)][chunk(8)][lane(32)] = {Bh0,Bh1,Bl0,Bl1} ----------------
__device__ __forceinline__ void stage_x(const float* __restrict__ xb, int pc, int tid,
                                        uint4* frag) {
    for (int u = tid; u < 4096; u += 256) {
        int lane = u & 31, chunk = (u >> 5) & 7, nt = u >> 8;
        int g = lane >> 2, t = lane & 3;
        int p = nt * 8 + g;
        int k0 = chunk * 16 + 2 * t;
        float v0 = 0.f, v1 = 0.f, v2 = 0.f, v3 = 0.f;
        if (p < pc) {
            v0 = __ldg(xb + (size_t)k0 * NPOS + p);
            v1 = __ldg(xb + (size_t)(k0 + 1) * NPOS + p);
            v2 = __ldg(xb + (size_t)(k0 + 8) * NPOS + p);
            v3 = __ldg(xb + (size_t)(k0 + 9) * NPOS + p);
        }
        uint4 r;
        r.x = packbf(v0, v1);
        r.y = packbf(v2, v3);
        r.z = packbf(v0 - rbf(v0), v1 - rbf(v1));
        r.w = packbf(v2 - rbf(v2), v3 - rbf(v3));
        frag[u] = r;
    }
}
// o source: natural [p][c]; channels (k0,k0+1) and (k0+8,k0+9) are contiguous float2s
__device__ __forceinline__ void stage_o(const float* __restrict__ ob, int pc, int tid,
                                        uint4* frag) {
    const float2* o2 = (const float2*)ob;
    for (int u = tid; u < 4096; u += 256) {
        int lane = u & 31, chunk = (u >> 5) & 7, nt = u >> 8;
        int g = lane >> 2, t = lane & 3;
        int p = nt * 8 + g;
        float2 rA = make_float2(0.f, 0.f), rB = make_float2(0.f, 0.f);
        if (p < pc) {
            rA = __ldg(o2 + (size_t)p * 64 + chunk * 8 + t);
            rB = __ldg(o2 + (size_t)p * 64 + chunk * 8 + t + 4);
        }
        uint4 r;
        r.x = packbf(rA.x, rA.y);
        r.y = packbf(rB.x, rB.y);
        r.z = packbf(rA.x - rbf(rA.x), rA.y - rbf(rA.y));
        r.w = packbf(rB.x - rbf(rB.x), rB.y - rbf(rB.y));
        frag[u] = r;
    }
}

// load A-fragments for weight w, M-group mg (32 rows = 2 strips)
__device__ __forceinline__ void load_afrag(int w, int mg, int lane,
                                           uint32_t aH[2][8][4], uint32_t aL[2][8][4]) {
    const uint4* PH = g_WFH + w*2048 + mg*512 + lane;
    const uint4* PL = g_WFL + w*2048 + mg*512 + lane;
#pragma unroll
    for (int s = 0; s < 2; s++)
#pragma unroll
        for (int ch = 0; ch < 8; ch++) {
            uint4 h = __ldg(PH + s*256 + ch*32);
            uint4 l = __ldg(PL + s*256 + ch*32);
            aH[s][ch][0] = h.x; aH[s][ch][1] = h.y; aH[s][ch][2] = h.z; aH[s][ch][3] = h.w;
            aL[s][ch][0] = l.x; aL[s][ch][1] = l.y; aL[s][ch][2] = l.z; aL[s][ch][3] = l.w;
        }
}

// 2-ntile × 2-strip GEMM, 3-term bf16 split: d = Ah*Bh + Al*Bh + Ah*Bl
__device__ __forceinline__ void gemm_pair(const uint4* frag, int nt0, int lane,
                                          const uint32_t aH[2][8][4], const uint32_t aL[2][8][4],
                                          float d[2][2][4]) {
#pragma unroll
    for (int j = 0; j < 2; j++)
#pragma unroll
        for (int s = 0; s < 2; s++)
#pragma unroll
            for (int i = 0; i < 4; i++) d[j][s][i] = 0.f;
    const uint4* f0 = frag + nt0*256 + lane;
    const uint4* f1 = f0 + 256;
#pragma unroll
    for (int ch = 0; ch < 8; ch++) {
        uint4 B0 = f0[ch*32];
        uint4 B1 = f1[ch*32];
        mma16(d[0][0], aH[0][ch], B0.x, B0.y);
        mma16(d[0][1], aH[1][ch], B0.x, B0.y);
        mma16(d[1][0], aH[0][ch], B1.x, B1.y);
        mma16(d[1][1], aH[1][ch], B1.x, B1.y);
        mma16(d[0][0], aL[0][ch], B0.x, B0.y);
        mma16(d[0][1], aL[1][ch], B0.x, B0.y);
        mma16(d[1][0], aL[0][ch], B1.x, B1.y);
        mma16(d[1][1], aL[1][ch], B1.x, B1.y);
        mma16(d[0][0], aH[0][ch], B0.z, B0.w);
        mma16(d[0][1], aH[1][ch], B0.z, B0.w);
        mma16(d[1][0], aH[0][ch], B1.z, B1.w);
        mma16(d[1][1], aH[1][ch], B1.z, B1.w);
    }
}

// =======================================================================
// kernelQV
// =======================================================================
#define SMEM_QV_BYTES (4096*16 + 128*VSP*4)
__global__ void __launch_bounds__(256, 1)
kernelQV(const float* __restrict__ x, const float* __restrict__ bq,
         const float* __restrict__ bv) {
    extern __shared__ uint4 frag[];
    float* vsm = (float*)(frag + 4096);

    int tid = threadIdx.x, wid = tid >> 5, lane = tid & 31;
    int mg = wid & 3, nh = wid >> 2;
    int g = lane >> 2, t = lane & 3;
    int ntbase = nh * 8;

    uint32_t aH[2][8][4], aL[2][8][4];
    float bqlo[2], bqhi[2], bvlo[2], bvhi[2];
#pragma unroll
    for (int s = 0; s < 2; s++) {
        int ch = mg*32 + s*16 + g;
        bqlo[s] = __ldg(bq + ch); bqhi[s] = __ldg(bq + ch + 8);
        bvlo[s] = __ldg(bv + ch); bvhi[s] = __ldg(bv + ch + 8);
    }
    int xk = lane & 15, yb = (lane >> 4) * 8;

    for (int tt = blockIdx.x; tt < NTILES; tt += gridDim.x) {
        int b = tt / NT, p0 = (tt % NT) * TP;
        int pc = min(TP, NPOS - p0);

        stage_x(x + ((size_t)b * CC) * NPOS + p0, pc, tid, frag);
        __syncthreads();

        // ---- phase Q ----
        load_afrag(0, mg, lane, aH, aL);
        float* qb = g_q + ((size_t)b * NPOS + p0) * CC;
#pragma unroll 1
        for (int ntp = 0; ntp < 4; ntp++) {
            int nt0 = ntbase + ntp * 2;
            float d[2][2][4];
            gemm_pair(frag, nt0, lane, aH, aL, d);
#pragma unroll
            for (int j = 0; j < 2; j++) {
                int c0 = (nt0 + j) * 8 + 2 * t;
#pragma unroll
                for (int s = 0; s < 2; s++) {
                    float* dd = d[j][s];
                    float v0 = fmaxf(dd[0] + bqlo[s], 0.f);
                    float v1 = fmaxf(dd[1] + bqlo[s], 0.f);
                    float v2 = fmaxf(dd[2] + bqhi[s], 0.f);
                    float v3 = fmaxf(dd[3] + bqhi[s], 0.f);
                    float me = fmaxf(v0, v2), mo = fmaxf(v1, v3);
#pragma unroll
                    for (int o = 4; o < 32; o <<= 1) {
                        me = fmaxf(me, __shfl_xor_sync(0xffffffffu, me, o));
                        mo = fmaxf(mo, __shfl_xor_sync(0xffffffffu, mo, o));
                    }
                    float e0 = __expf(0.25f*(v0 - me)), e2 = __expf(0.25f*(v2 - me));
                    float e1 = __expf(0.25f*(v1 - mo)), e3 = __expf(0.25f*(v3 - mo));
                    float se = e0 + e2, so = e1 + e3;
#pragma unroll
                    for (int o = 4; o < 32; o <<= 1) {
                        se += __shfl_xor_sync(0xffffffffu, se, o);
                        so += __shfl_xor_sync(0xffffffffu, so, o);
                    }
                    float ie = 1.f / se, io = 1.f / so;
                    int ch = mg*32 + s*16 + g;
                    if (c0 < pc) {
                        qb[(size_t)c0 * CC + ch]     = e0 * ie;
                        qb[(size_t)c0 * CC + ch + 8] = e2 * ie;
                    }
                    if (c0 + 1 < pc) {
                        qb[(size_t)(c0+1) * CC + ch]     = e1 * io;
                        qb[(size_t)(c0+1) * CC + ch + 8] = e3 * io;
                    }
                }
            }
        }

        // ---- phase V ----
        load_afrag(1, mg, lane, aH, aL);
#pragma unroll 1
        for (int ntp = 0; ntp < 4; ntp++) {
            int nt0 = ntbase + ntp * 2;
            float d[2][2][4];
            gemm_pair(frag, nt0, lane, aH, aL, d);
#pragma unroll
            for (int j = 0; j < 2; j++) {
                int c0 = (nt0 + j) * 8 + 2 * t;
#pragma unroll
                for (int s = 0; s < 2; s++) {
                    float* dd = d[j][s];
                    int ch = mg*32 + s*16 + g;
                    vsm[ch * VSP + c0]           = fmaxf(dd[0] + bvlo[s], 0.f);
                    vsm[ch * VSP + c0 + 1]       = fmaxf(dd[1] + bvlo[s], 0.f);
                    vsm[(ch + 8) * VSP + c0]     = fmaxf(dd[2] + bvhi[s], 0.f);
                    vsm[(ch + 8) * VSP + c0 + 1] = fmaxf(dd[3] + bvhi[s], 0.f);
                }
            }
        }
        __syncthreads();

        // ---- kv accumulation: warp = head ----
        {
            int h = wid;
            const float* keyh = g_key + (size_t)h * (LLL * NNN * DKK);
            for (int l = 0; l < LLL; l++) {
                float a8[8];
#pragma unroll
                for (int j = 0; j < 8; j++) a8[j] = 0.f;
                int s = ((l - p0) % 12 + 12) % 12;
                for (int pp = s; pp < pc; pp += 12) {
                    int n = (p0 + pp) / 12;
                    float kx = __ldg(&keyh[((size_t)l * NNN + n) * DKK + xk]);
                    const float* vb = vsm + (h * 16 + yb) * VSP + pp;
#pragma unroll
                    for (int j = 0; j < 8; j++) a8[j] = fmaf(kx, vb[j * VSP], a8[j]);
                }
                float* kvp = g_kv + ((((size_t)b * LLL + l) * HEAD + h) * DKK + xk) * DKK + yb;
#pragma unroll
                for (int j = 0; j < 8; j++) atomicAdd(kvp + j, a8[j]);
            }
        }
        __syncthreads();
    }
}

// =======================================================================
// kernelB1: o[b,p,:] = q[b,p,:] @ kv[b,l(p)]  (natural layout)
// =======================================================================
__global__ void __launch_bounds__(256, 4)
kernelB1() {
    __shared__ float kvs[HEAD*DKK*DKK];
    int b = blockIdx.z, l = blockIdx.y;
    int tid = threadIdx.x;

    const float* kvb = g_kv + ((size_t)b * LLL + l) * (HEAD * DKK * DKK);
    for (int i = tid; i < HEAD*DKK*DKK; i += 256) kvs[i] = kvb[i];
    __syncthreads();

    int n = blockIdx.x * 256 + tid;
    if (n >= NNN) return;
    int P = n * 12 + l;
    const float* qr = g_q + ((size_t)b * NPOS + P) * CC;
    float* orow = g_o + ((size_t)b * NPOS + P) * CC;

#pragma unroll
    for (int h = 0; h < HEAD; h++) {
        const float4* q4 = (const float4*)(qr + h * 16);
        float4 a0 = q4[0], a1 = q4[1], a2 = q4[2], a3 = q4[3];
        float q16[16] = {a0.x,a0.y,a0.z,a0.w, a1.x,a1.y,a1.z,a1.w,
                         a2.x,a2.y,a2.z,a2.w, a3.x,a3.y,a3.z,a3.w};
        float o16[16];
#pragma unroll
        for (int y = 0; y < 16; y++) o16[y] = 0.f;
        const float* kvh = kvs + h * 256;
#pragma unroll
        for (int xq = 0; xq < 16; xq++) {
            float qv = q16[xq];
            const float4* kr = (const float4*)(kvh + xq * 16);
            float4 k0 = kr[0], k1 = kr[1], k2 = kr[2], k3 = kr[3];
            o16[0]  = fmaf(qv, k0.x, o16[0]);  o16[1]  = fmaf(qv, k0.y, o16[1]);
            o16[2]  = fmaf(qv, k0.z, o16[2]);  o16[3]  = fmaf(qv, k0.w, o16[3]);
            o16[4]  = fmaf(qv, k1.x, o16[4]);  o16[5]  = fmaf(qv, k1.y, o16[5]);
            o16[6]  = fmaf(qv, k1.z, o16[6]);  o16[7]  = fmaf(qv, k1.w, o16[7]);
            o16[8]  = fmaf(qv, k2.x, o16[8]);  o16[9]  = fmaf(qv, k2.y, o16[9]);
            o16[10] = fmaf(qv, k2.z, o16[10]); o16[11] = fmaf(qv, k2.w, o16[11]);
            o16[12] = fmaf(qv, k3.x, o16[12]); o16[13] = fmaf(qv, k3.y, o16[13]);
            o16[14] = fmaf(qv, k3.z, o16[14]); o16[15] = fmaf(qv, k3.w, o16[15]);
        }
        float4* od = (float4*)(orow + h * 16);
        od[0] = make_float4(o16[0],  o16[1],  o16[2],  o16[3]);
        od[1] = make_float4(o16[4],  o16[5],  o16[6],  o16[7]);
        od[2] = make_float4(o16[8],  o16[9],  o16[10], o16[11]);
        od[3] = make_float4(o16[12], o16[13], o16[14], o16[15]);
    }
}

// =======================================================================
// kernelB2: out = relu(Wc o + bc) -> out[b][c][p]
// =======================================================================
#define SMEM_B2_BYTES (4096*16)
__global__ void __launch_bounds__(256, 1)
kernelB2(const float* __restrict__ bc, float* __restrict__ out) {
    extern __shared__ uint4 frag[];

    int tid = threadIdx.x, wid = tid >> 5, lane = tid & 31;
    int mg = wid & 3, nh = wid >> 2;
    int g = lane >> 2, t = lane & 3;
    int ntbase = nh * 8;

    uint32_t aH[2][8][4], aL[2][8][4];
    load_afrag(2, mg, lane, aH, aL);
    float bclo[2], bchi[2];
#pragma unroll
    for (int s = 0; s < 2; s++) {
        int ch = mg*32 + s*16 + g;
        bclo[s] = __ldg(bc + ch); bchi[s] = __ldg(bc + ch + 8);
    }

    for (int tt = blockIdx.x; tt < NTILES; tt += gridDim.x) {
        int b = tt / NT, p0 = (tt % NT) * TP;
        int pc = min(TP, NPOS - p0);

        stage_o(g_o + ((size_t)b * NPOS + p0) * CC, pc, tid, frag);
        __syncthreads();

        float* ob = out + (size_t)b * CC * NPOS + p0;
#pragma unroll 1
        for (int ntp = 0; ntp < 4; ntp++) {
            int nt0 = ntbase + ntp * 2;
            float d[2][2][4];
            gemm_pair(frag, nt0, lane, aH, aL, d);
#pragma unroll
            for (int j = 0; j < 2; j++) {
                int c0 = (nt0 + j) * 8 + 2 * t;
#pragma unroll
                for (int s = 0; s < 2; s++) {
                    float* dd = d[j][s];
                    int ch = mg*32 + s*16 + g;
                    float w0 = fmaxf(dd[0] + bclo[s], 0.f);
                    float w1 = fmaxf(dd[1] + bclo[s], 0.f);
                    float w2 = fmaxf(dd[2] + bchi[s], 0.f);
                    float w3 = fmaxf(dd[3] + bchi[s], 0.f);
                    if (c0 + 1 < pc) {
                        *(float2*)(ob + (size_t)ch * NPOS + c0)       = make_float2(w0, w1);
                        *(float2*)(ob + (size_t)(ch + 8) * NPOS + c0) = make_float2(w2, w3);
                    } else if (c0 < pc) {
                        ob[(size_t)ch * NPOS + c0]       = w0;
                        ob[(size_t)(ch + 8) * NPOS + c0] = w2;
                    }
                }
            }
        }
        __syncthreads();
    }
}

// ---------------- launch ----------------
extern "C" void kernel_launch(void* const* d_in, const int* in_sizes, int n_in,
                              void* d_out, int out_size) {
    (void)in_sizes; (void)n_in; (void)out_size;
    const float* x      = (const float*)d_in[0];
    const float* Wq     = (const float*)d_in[1];
    const float* bq     = (const float*)d_in[2];
    const float* Wv     = (const float*)d_in[3];
    const float* bv     = (const float*)d_in[4];
    const float* Wc     = (const float*)d_in[5];
    const float* bc     = (const float*)d_in[6];
    const float* s_bank = (const float*)d_in[7];
    float* out = (float*)d_out;

    cudaFuncSetAttribute(kernelQV, cudaFuncAttributeMaxDynamicSharedMemorySize, SMEM_QV_BYTES);
    cudaFuncSetAttribute(kernelB2, cudaFuncAttributeMaxDynamicSharedMemorySize, SMEM_B2_BYTES);

    k_prep_w<<<3, 256>>>(Wq, Wv, Wc);
    k_key<<<(HEAD*LLL*NNN + 255) / 256, 256>>>(s_bank);
    k_zero_kv<<<(BB*LLL*HEAD*DKK*DKK/4) / 256, 256>>>();
    kernelQV<<<GRID_PERS, 256, SMEM_QV_BYTES>>>(x, bq, bv);
    kernelB1<<<dim3((NNN + 255) / 256, LLL, BB), 256>>>();
    kernelB2<<<GRID_PERS, 256, SMEM_B2_BYTES>>>(bc, out);
}

// round 7
// speedup vs baseline: 2.0364x; 1.5677x over previous
#include <cuda_runtime.h>
#include <cuda_bf16.h>
#include <cstdint>

#define BB 16
#define CC 128
#define HEAD 8
#define DKK 16
#define NNN 2500
#define LLL 12
#define NPOS (NNN*LLL)
#define TP 128
#define NT ((NPOS + TP - 1)/TP)      /* 235 */
#define NTILES (NT*BB)               /* 3760 */
#define GRID_PERS 152
#define NTHR 512

// ---------------- device scratch ----------------
__device__ __align__(16) uint4 g_WFH[3*2048];   // bf16 A-frags hi: [w][strip(8)][chunk(8)][lane(32)]
__device__ __align__(16) uint4 g_WFL[3*2048];   // bf16 A-frags lo
__device__ __align__(16) float g_key[HEAD*LLL*NNN*DKK];
__device__ __align__(16) float g_kv[BB*LLL*HEAD*DKK*DKK];
__device__ __align__(16) float g_q[(size_t)BB*NPOS*CC];   // [b][p][c]
__device__ __align__(16) float g_v[(size_t)BB*NPOS*CC];   // [b][p][c]
__device__ __align__(16) float g_o[(size_t)BB*NPOS*CC];   // [b][p][c]

// ---------------- helpers ----------------
__device__ __forceinline__ float rbf(float x) {
    return __bfloat162float(__float2bfloat16(x));
}
__device__ __forceinline__ uint32_t packbf(float vlo, float vhi) {
    uint32_t r;
    asm("cvt.rn.bf16x2.f32 %0, %1, %2;" : "=r"(r) : "f"(vhi), "f"(vlo));
    return r;
}
__device__ __forceinline__ void mma16(float d[4], const uint32_t a[4], uint32_t b0, uint32_t b1) {
    asm volatile("mma.sync.aligned.m16n8k16.row.col.f32.bf16.bf16.f32 "
        "{%0,%1,%2,%3}, {%4,%5,%6,%7}, {%8,%9}, {%0,%1,%2,%3};"
        : "+f"(d[0]), "+f"(d[1]), "+f"(d[2]), "+f"(d[3])
        : "r"(a[0]), "r"(a[1]), "r"(a[2]), "r"(a[3]), "r"(b0), "r"(b1));
}

// ---------------- prep: weight A-fragments (bf16 hi/lo), strip = 16 rows ----------------
__global__ void k_prep_w(const float* __restrict__ Wq, const float* __restrict__ Wv,
                         const float* __restrict__ Wc) {
    int w = blockIdx.x;
    const float* src = (w == 0) ? Wq : (w == 1) ? Wv : Wc;
    for (int f = threadIdx.x; f < 2048; f += 256) {
        int lane = f & 31, chunk = (f >> 5) & 7, strip = (f >> 8) & 7;
        int g = lane >> 2, t = lane & 3;
        int m0 = strip * 16 + g, m1 = m0 + 8;
        int k0 = chunk * 16 + 2 * t;
        float w00 = src[m0*128 + k0],     w01 = src[m0*128 + k0 + 1];
        float w10 = src[m1*128 + k0],     w11 = src[m1*128 + k0 + 1];
        float w02 = src[m0*128 + k0 + 8], w03 = src[m0*128 + k0 + 9];
        float w12 = src[m1*128 + k0 + 8], w13 = src[m1*128 + k0 + 9];
        uint4 H, L;
        H.x = packbf(w00, w01); H.y = packbf(w10, w11);
        H.z = packbf(w02, w03); H.w = packbf(w12, w13);
        L.x = packbf(w00 - rbf(w00), w01 - rbf(w01));
        L.y = packbf(w10 - rbf(w10), w11 - rbf(w11));
        L.z = packbf(w02 - rbf(w02), w03 - rbf(w03));
        L.w = packbf(w12 - rbf(w12), w13 - rbf(w13));
        g_WFH[w*2048 + f] = H;
        g_WFL[w*2048 + f] = L;
    }
}

__global__ void k_key(const float* __restrict__ s_bank) {
    int r = blockIdx.x * 256 + threadIdx.x;
    if (r >= HEAD*LLL*NNN) return;
    const float4* src = (const float4*)(s_bank + (size_t)r * 16);
    float4 v0 = src[0], v1 = src[1], v2 = src[2], v3 = src[3];
    float v[16] = {v0.x,v0.y,v0.z,v0.w, v1.x,v1.y,v1.z,v1.w,
                   v2.x,v2.y,v2.z,v2.w, v3.x,v3.y,v3.z,v3.w};
    float mx = v[0];
#pragma unroll
    for (int i = 1; i < 16; i++) mx = fmaxf(mx, v[i]);
    float s = 0.f;
#pragma unroll
    for (int i = 0; i < 16; i++) { v[i] = __expf(0.25f * (v[i] - mx)); s += v[i]; }
    float inv = 1.f / s;
#pragma unroll
    for (int i = 0; i < 16; i++) v[i] *= inv;
    float4* dst = (float4*)(g_key + (size_t)r * 16);
    dst[0] = make_float4(v[0],v[1],v[2],v[3]);
    dst[1] = make_float4(v[4],v[5],v[6],v[7]);
    dst[2] = make_float4(v[8],v[9],v[10],v[11]);
    dst[3] = make_float4(v[12],v[13],v[14],v[15]);
}

__global__ void k_zero_kv() {
    int i = blockIdx.x * 256 + threadIdx.x;
    ((float4*)g_kv)[i] = make_float4(0.f, 0.f, 0.f, 0.f);
}

// ---------------- staging: B-fragments frag[nt(16)][chunk(8)][lane(32)] = {Bh0,Bh1,Bl0,Bl1} ----------------
__device__ __forceinline__ void stage_x(const float* __restrict__ xb, int pc, int tid,
                                        uint4* frag) {
    for (int u = tid; u < 4096; u += NTHR) {
        int lane = u & 31, chunk = (u >> 5) & 7, nt = u >> 8;
        int g = lane >> 2, t = lane & 3;
        int p = nt * 8 + g;
        int k0 = chunk * 16 + 2 * t;
        float v0 = 0.f, v1 = 0.f, v2 = 0.f, v3 = 0.f;
        if (p < pc) {
            v0 = __ldg(xb + (size_t)k0 * NPOS + p);
            v1 = __ldg(xb + (size_t)(k0 + 1) * NPOS + p);
            v2 = __ldg(xb + (size_t)(k0 + 8) * NPOS + p);
            v3 = __ldg(xb + (size_t)(k0 + 9) * NPOS + p);
        }
        uint4 r;
        r.x = packbf(v0, v1);
        r.y = packbf(v2, v3);
        r.z = packbf(v0 - rbf(v0), v1 - rbf(v1));
        r.w = packbf(v2 - rbf(v2), v3 - rbf(v3));
        frag[u] = r;
    }
}
__device__ __forceinline__ void stage_o(const float* __restrict__ ob, int pc, int tid,
                                        uint4* frag) {
    const float2* o2 = (const float2*)ob;
    for (int u = tid; u < 4096; u += NTHR) {
        int lane = u & 31, chunk = (u >> 5) & 7, nt = u >> 8;
        int g = lane >> 2, t = lane & 3;
        int p = nt * 8 + g;
        float2 rA = make_float2(0.f, 0.f), rB = make_float2(0.f, 0.f);
        if (p < pc) {
            rA = __ldg(o2 + (size_t)p * 64 + chunk * 8 + t);
            rB = __ldg(o2 + (size_t)p * 64 + chunk * 8 + t + 4);
        }
        uint4 r;
        r.x = packbf(rA.x, rA.y);
        r.y = packbf(rB.x, rB.y);
        r.z = packbf(rA.x - rbf(rA.x), rA.y - rbf(rA.y));
        r.w = packbf(rB.x - rbf(rB.x), rB.y - rbf(rB.y));
        frag[u] = r;
    }
}

// load A-frags for weight w, strip (16 rows)
__device__ __forceinline__ void load_afrag(int w, int strip, int lane,
                                           uint32_t aH[8][4], uint32_t aL[8][4]) {
    const uint4* PH = g_WFH + w*2048 + strip*256 + lane;
    const uint4* PL = g_WFL + w*2048 + strip*256 + lane;
#pragma unroll
    for (int ch = 0; ch < 8; ch++) {
        uint4 h = __ldg(PH + ch*32);
        uint4 l = __ldg(PL + ch*32);
        aH[ch][0] = h.x; aH[ch][1] = h.y; aH[ch][2] = h.z; aH[ch][3] = h.w;
        aL[ch][0] = l.x; aL[ch][1] = l.y; aL[ch][2] = l.z; aL[ch][3] = l.w;
    }
}

// 2-ntile GEMM, 3-term bf16 split
__device__ __forceinline__ void gemm_pair(const uint4* frag, int nt0, int lane,
                                          const uint32_t aH[8][4], const uint32_t aL[8][4],
                                          float d[2][4]) {
#pragma unroll
    for (int j = 0; j < 2; j++)
#pragma unroll
        for (int i = 0; i < 4; i++) d[j][i] = 0.f;
    const uint4* f0 = frag + nt0*256 + lane;
    const uint4* f1 = f0 + 256;
#pragma unroll
    for (int ch = 0; ch < 8; ch++) {
        uint4 B0 = f0[ch*32];
        uint4 B1 = f1[ch*32];
        mma16(d[0], aH[ch], B0.x, B0.y);
        mma16(d[1], aH[ch], B1.x, B1.y);
        mma16(d[0], aL[ch], B0.x, B0.y);
        mma16(d[1], aL[ch], B1.x, B1.y);
        mma16(d[0], aH[ch], B0.z, B0.w);
        mma16(d[1], aH[ch], B1.z, B1.w);
    }
}

// =======================================================================
// kernelQV: 512 threads, 16 warps = 8 strips x 2 N-halves
// =======================================================================
#define SMEM_FRAG_BYTES (4096*16)
__global__ void __launch_bounds__(NTHR, 1)
kernelQV(const float* __restrict__ x, const float* __restrict__ bq,
         const float* __restrict__ bv) {
    extern __shared__ uint4 frag[];

    int tid = threadIdx.x, wid = tid >> 5, lane = tid & 31;
    int mg = wid & 7, nh = wid >> 3;
    int g = lane >> 2, t = lane & 3;
    int ntbase = nh * 8;
    int ch = mg * 16 + g;

    uint32_t aH[8][4], aL[8][4];
    float bqlo = __ldg(bq + ch), bqhi = __ldg(bq + ch + 8);
    float bvlo = __ldg(bv + ch), bvhi = __ldg(bv + ch + 8);

    for (int tt = blockIdx.x; tt < NTILES; tt += gridDim.x) {
        int b = tt / NT, p0 = (tt % NT) * TP;
        int pc = min(TP, NPOS - p0);

        stage_x(x + ((size_t)b * CC) * NPOS + p0, pc, tid, frag);
        __syncthreads();

        // ---- phase Q ----
        load_afrag(0, mg, lane, aH, aL);
        float* qb = g_q + ((size_t)b * NPOS + p0) * CC;
#pragma unroll 1
        for (int ntp = 0; ntp < 4; ntp++) {
            int nt0 = ntbase + ntp * 2;
            float d[2][4];
            gemm_pair(frag, nt0, lane, aH, aL, d);
#pragma unroll
            for (int j = 0; j < 2; j++) {
                int c0 = (nt0 + j) * 8 + 2 * t;
                float v0 = fmaxf(d[j][0] + bqlo, 0.f);
                float v1 = fmaxf(d[j][1] + bqlo, 0.f);
                float v2 = fmaxf(d[j][2] + bqhi, 0.f);
                float v3 = fmaxf(d[j][3] + bqhi, 0.f);
                float me = fmaxf(v0, v2), mo = fmaxf(v1, v3);
#pragma unroll
                for (int o = 4; o < 32; o <<= 1) {
                    me = fmaxf(me, __shfl_xor_sync(0xffffffffu, me, o));
                    mo = fmaxf(mo, __shfl_xor_sync(0xffffffffu, mo, o));
                }
                float e0 = __expf(0.25f*(v0 - me)), e2 = __expf(0.25f*(v2 - me));
                float e1 = __expf(0.25f*(v1 - mo)), e3 = __expf(0.25f*(v3 - mo));
                float se = e0 + e2, so = e1 + e3;
#pragma unroll
                for (int o = 4; o < 32; o <<= 1) {
                    se += __shfl_xor_sync(0xffffffffu, se, o);
                    so += __shfl_xor_sync(0xffffffffu, so, o);
                }
                float ie = 1.f / se, io = 1.f / so;
                if (c0 < pc) {
                    qb[(size_t)c0 * CC + ch]     = e0 * ie;
                    qb[(size_t)c0 * CC + ch + 8] = e2 * ie;
                }
                if (c0 + 1 < pc) {
                    qb[(size_t)(c0+1) * CC + ch]     = e1 * io;
                    qb[(size_t)(c0+1) * CC + ch + 8] = e3 * io;
                }
            }
        }

        // ---- phase V: write v to global ----
        load_afrag(1, mg, lane, aH, aL);
        float* vb = g_v + ((size_t)b * NPOS + p0) * CC;
#pragma unroll 1
        for (int ntp = 0; ntp < 4; ntp++) {
            int nt0 = ntbase + ntp * 2;
            float d[2][4];
            gemm_pair(frag, nt0, lane, aH, aL, d);
#pragma unroll
            for (int j = 0; j < 2; j++) {
                int c0 = (nt0 + j) * 8 + 2 * t;
                if (c0 < pc) {
                    vb[(size_t)c0 * CC + ch]     = fmaxf(d[j][0] + bvlo, 0.f);
                    vb[(size_t)c0 * CC + ch + 8] = fmaxf(d[j][2] + bvhi, 0.f);
                }
                if (c0 + 1 < pc) {
                    vb[(size_t)(c0+1) * CC + ch]     = fmaxf(d[j][1] + bvlo, 0.f);
                    vb[(size_t)(c0+1) * CC + ch + 8] = fmaxf(d[j][3] + bvhi, 0.f);
                }
            }
        }
        __syncthreads();
    }
}

// =======================================================================
// k_kv: kv[b,l,h,x,y] += sum_n key[h,l,n,x] * v[b, n*12+l, h*16+y]
// grid (nchunk=10, l=12, b=16), 256 threads, warp = head
// =======================================================================
#define NCHUNK 250
__global__ void __launch_bounds__(256, 4)
k_kv() {
    int nc = blockIdx.x, l = blockIdx.y, b = blockIdx.z;
    int tid = threadIdx.x, wid = tid >> 5, lane = tid & 31;
    int h = wid;
    int xk = lane & 15, yb = (lane >> 4) * 8;
    int n0 = nc * NCHUNK;

    const float* keyh = g_key + (((size_t)h * LLL + l) * NNN) * DKK;
    const float* vbase = g_v + ((size_t)b * NPOS + l) * CC + h * 16 + yb;

    float acc[8];
#pragma unroll
    for (int j = 0; j < 8; j++) acc[j] = 0.f;

#pragma unroll 2
    for (int n = n0; n < n0 + NCHUNK; n++) {
        float kx = __ldg(keyh + (size_t)n * DKK + xk);
        const float4* vp = (const float4*)(vbase + (size_t)n * 12 * CC);
        float4 vA = __ldg(vp), vB = __ldg(vp + 1);
        acc[0] = fmaf(kx, vA.x, acc[0]); acc[1] = fmaf(kx, vA.y, acc[1]);
        acc[2] = fmaf(kx, vA.z, acc[2]); acc[3] = fmaf(kx, vA.w, acc[3]);
        acc[4] = fmaf(kx, vB.x, acc[4]); acc[5] = fmaf(kx, vB.y, acc[5]);
        acc[6] = fmaf(kx, vB.z, acc[6]); acc[7] = fmaf(kx, vB.w, acc[7]);
    }
    float* kvp = g_kv + ((((size_t)b * LLL + l) * HEAD + h) * DKK + xk) * DKK + yb;
#pragma unroll
    for (int j = 0; j < 8; j++) atomicAdd(kvp + j, acc[j]);
}

// =======================================================================
// kernelB1: o[b,p,:] = q[b,p,:] @ kv[b,l(p)]
// =======================================================================
__global__ void __launch_bounds__(256, 4)
kernelB1() {
    __shared__ float kvs[HEAD*DKK*DKK];
    int b = blockIdx.z, l = blockIdx.y;
    int tid = threadIdx.x;

    const float* kvb = g_kv + ((size_t)b * LLL + l) * (HEAD * DKK * DKK);
    for (int i = tid; i < HEAD*DKK*DKK; i += 256) kvs[i] = kvb[i];
    __syncthreads();

    int n = blockIdx.x * 256 + tid;
    if (n >= NNN) return;
    int P = n * 12 + l;
    const float* qr = g_q + ((size_t)b * NPOS + P) * CC;
    float* orow = g_o + ((size_t)b * NPOS + P) * CC;

#pragma unroll
    for (int h = 0; h < HEAD; h++) {
        const float4* q4 = (const float4*)(qr + h * 16);
        float4 a0 = q4[0], a1 = q4[1], a2 = q4[2], a3 = q4[3];
        float q16[16] = {a0.x,a0.y,a0.z,a0.w, a1.x,a1.y,a1.z,a1.w,
                         a2.x,a2.y,a2.z,a2.w, a3.x,a3.y,a3.z,a3.w};
        float o16[16];
#pragma unroll
        for (int y = 0; y < 16; y++) o16[y] = 0.f;
        const float* kvh = kvs + h * 256;
#pragma unroll
        for (int xq = 0; xq < 16; xq++) {
            float qv = q16[xq];
            const float4* kr = (const float4*)(kvh + xq * 16);
            float4 k0 = kr[0], k1 = kr[1], k2 = kr[2], k3 = kr[3];
            o16[0]  = fmaf(qv, k0.x, o16[0]);  o16[1]  = fmaf(qv, k0.y, o16[1]);
            o16[2]  = fmaf(qv, k0.z, o16[2]);  o16[3]  = fmaf(qv, k0.w, o16[3]);
            o16[4]  = fmaf(qv, k1.x, o16[4]);  o16[5]  = fmaf(qv, k1.y, o16[5]);
            o16[6]  = fmaf(qv, k1.z, o16[6]);  o16[7]  = fmaf(qv, k1.w, o16[7]);
            o16[8]  = fmaf(qv, k2.x, o16[8]);  o16[9]  = fmaf(qv, k2.y, o16[9]);
            o16[10] = fmaf(qv, k2.z, o16[10]); o16[11] = fmaf(qv, k2.w, o16[11]);
            o16[12] = fmaf(qv, k3.x, o16[12]); o16[13] = fmaf(qv, k3.y, o16[13]);
            o16[14] = fmaf(qv, k3.z, o16[14]); o16[15] = fmaf(qv, k3.w, o16[15]);
        }
        float4* od = (float4*)(orow + h * 16);
        od[0] = make_float4(o16[0],  o16[1],  o16[2],  o16[3]);
        od[1] = make_float4(o16[4],  o16[5],  o16[6],  o16[7]);
        od[2] = make_float4(o16[8],  o16[9],  o16[10], o16[11]);
        od[3] = make_float4(o16[12], o16[13], o16[14], o16[15]);
    }
}

// =======================================================================
// kernelB2: out = relu(Wc o + bc) -> out[b][c][p], 512 threads
// =======================================================================
__global__ void __launch_bounds__(NTHR, 1)
kernelB2(const float* __restrict__ bc, float* __restrict__ out) {
    extern __shared__ uint4 frag[];

    int tid = threadIdx.x, wid = tid >> 5, lane = tid & 31;
    int mg = wid & 7, nh = wid >> 3;
    int g = lane >> 2, t = lane & 3;
    int ntbase = nh * 8;
    int ch = mg * 16 + g;

    uint32_t aH[8][4], aL[8][4];
    load_afrag(2, mg, lane, aH, aL);
    float bclo = __ldg(bc + ch), bchi = __ldg(bc + ch + 8);

    for (int tt = blockIdx.x; tt < NTILES; tt += gridDim.x) {
        int b = tt / NT, p0 = (tt % NT) * TP;
        int pc = min(TP, NPOS - p0);

        stage_o(g_o + ((size_t)b * NPOS + p0) * CC, pc, tid, frag);
        __syncthreads();

        float* ob = out + (size_t)b * CC * NPOS + p0;
#pragma unroll 1
        for (int ntp = 0; ntp < 4; ntp++) {
            int nt0 = ntbase + ntp * 2;
            float d[2][4];
            gemm_pair(frag, nt0, lane, aH, aL, d);
#pragma unroll
            for (int j = 0; j < 2; j++) {
                int c0 = (nt0 + j) * 8 + 2 * t;
                float w0 = fmaxf(d[j][0] + bclo, 0.f);
                float w1 = fmaxf(d[j][1] + bclo, 0.f);
                float w2 = fmaxf(d[j][2] + bchi, 0.f);
                float w3 = fmaxf(d[j][3] + bchi, 0.f);
                if (c0 + 1 < pc) {
                    *(float2*)(ob + (size_t)ch * NPOS + c0)       = make_float2(w0, w1);
                    *(float2*)(ob + (size_t)(ch + 8) * NPOS + c0) = make_float2(w2, w3);
                } else if (c0 < pc) {
                    ob[(size_t)ch * NPOS + c0]       = w0;
                    ob[(size_t)(ch + 8) * NPOS + c0] = w2;
                }
            }
        }
        __syncthreads();
    }
}

// ---------------- launch ----------------
extern "C" void kernel_launch(void* const* d_in, const int* in_sizes, int n_in,
                              void* d_out, int out_size) {
    (void)in_sizes; (void)n_in; (void)out_size;
    const float* x      = (const float*)d_in[0];
    const float* Wq     = (const float*)d_in[1];
    const float* bq     = (const float*)d_in[2];
    const float* Wv     = (const float*)d_in[3];
    const float* bv     = (const float*)d_in[4];
    const float* Wc     = (const float*)d_in[5];
    const float* bc     = (const float*)d_in[6];
    const float* s_bank = (const float*)d_in[7];
    float* out = (float*)d_out;

    cudaFuncSetAttribute(kernelQV, cudaFuncAttributeMaxDynamicSharedMemorySize, SMEM_FRAG_BYTES);
    cudaFuncSetAttribute(kernelB2, cudaFuncAttributeMaxDynamicSharedMemorySize, SMEM_FRAG_BYTES);

    k_prep_w<<<3, 256>>>(Wq, Wv, Wc);
    k_key<<<(HEAD*LLL*NNN + 255) / 256, 256>>>(s_bank);
    k_zero_kv<<<(BB*LLL*HEAD*DKK*DKK/4) / 256, 256>>>();
    kernelQV<<<GRID_PERS, NTHR, SMEM_FRAG_BYTES>>>(x, bq, bv);
    k_kv<<<dim3(NNN/NCHUNK, LLL, BB), 256>>>();
    kernelB1<<<dim3((NNN + 255) / 256, LLL, BB), 256>>>();
    kernelB2<<<GRID_PERS, NTHR, SMEM_FRAG_BYTES>>>(bc, out);
}

// round 8
// speedup vs baseline: 2.2926x; 1.1258x over previous
#include <cuda_runtime.h>
#include <cuda_bf16.h>
#include <cstdint>

#define BB 16
#define CC 128
#define HEAD 8
#define DKK 16
#define NNN 2500
#define LLL 12
#define NPOS (NNN*LLL)
#define TP 128
#define NT ((NPOS + TP - 1)/TP)      /* 235 */
#define NTILES (NT*BB)               /* 3760 */
#define GRID_PERS 152
#define NTHR 512

// ---------------- device scratch ----------------
__device__ __align__(16) uint4 g_WFH[3*2048];   // bf16 A-frags hi: [w][strip(8)][chunk(8)][lane(32)]
__device__ __align__(16) uint4 g_WFL[3*2048];   // bf16 A-frags lo
__device__ __align__(16) float g_key[HEAD*LLL*NNN*DKK];
__device__ __align__(16) float g_kv[BB*LLL*HEAD*DKK*DKK];
__device__ __align__(16) float g_q[(size_t)BB*NPOS*CC];   // [b][p][c]
__device__ __align__(16) float g_v[(size_t)BB*NPOS*CC];   // [b][p][c]
__device__ __align__(16) float g_o[(size_t)BB*NPOS*CC];   // [b][p][c]

// ---------------- helpers ----------------
__device__ __forceinline__ float rbf(float x) {
    return __bfloat162float(__float2bfloat16(x));
}
__device__ __forceinline__ uint32_t packbf(float vlo, float vhi) {
    uint32_t r;
    asm("cvt.rn.bf16x2.f32 %0, %1, %2;" : "=r"(r) : "f"(vhi), "f"(vlo));
    return r;
}
__device__ __forceinline__ void mma16(float d[4], const uint32_t a[4], uint32_t b0, uint32_t b1) {
    asm volatile("mma.sync.aligned.m16n8k16.row.col.f32.bf16.bf16.f32 "
        "{%0,%1,%2,%3}, {%4,%5,%6,%7}, {%8,%9}, {%0,%1,%2,%3};"
        : "+f"(d[0]), "+f"(d[1]), "+f"(d[2]), "+f"(d[3])
        : "r"(a[0]), "r"(a[1]), "r"(a[2]), "r"(a[3]), "r"(b0), "r"(b1));
}

// ---------------- prep: weight A-fragments (bf16 hi/lo), strip = 16 rows ----------------
__global__ void k_prep_w(const float* __restrict__ Wq, const float* __restrict__ Wv,
                         const float* __restrict__ Wc) {
    int w = blockIdx.x;
    const float* src = (w == 0) ? Wq : (w == 1) ? Wv : Wc;
    for (int f = threadIdx.x; f < 2048; f += 256) {
        int lane = f & 31, chunk = (f >> 5) & 7, strip = (f >> 8) & 7;
        int g = lane >> 2, t = lane & 3;
        int m0 = strip * 16 + g, m1 = m0 + 8;
        int k0 = chunk * 16 + 2 * t;
        float w00 = src[m0*128 + k0],     w01 = src[m0*128 + k0 + 1];
        float w10 = src[m1*128 + k0],     w11 = src[m1*128 + k0 + 1];
        float w02 = src[m0*128 + k0 + 8], w03 = src[m0*128 + k0 + 9];
        float w12 = src[m1*128 + k0 + 8], w13 = src[m1*128 + k0 + 9];
        uint4 H, L;
        H.x = packbf(w00, w01); H.y = packbf(w10, w11);
        H.z = packbf(w02, w03); H.w = packbf(w12, w13);
        L.x = packbf(w00 - rbf(w00), w01 - rbf(w01));
        L.y = packbf(w10 - rbf(w10), w11 - rbf(w11));
        L.z = packbf(w02 - rbf(w02), w03 - rbf(w03));
        L.w = packbf(w12 - rbf(w12), w13 - rbf(w13));
        g_WFH[w*2048 + f] = H;
        g_WFL[w*2048 + f] = L;
    }
}

__global__ void k_key(const float* __restrict__ s_bank) {
    int r = blockIdx.x * 256 + threadIdx.x;
    if (r >= HEAD*LLL*NNN) return;
    const float4* src = (const float4*)(s_bank + (size_t)r * 16);
    float4 v0 = src[0], v1 = src[1], v2 = src[2], v3 = src[3];
    float v[16] = {v0.x,v0.y,v0.z,v0.w, v1.x,v1.y,v1.z,v1.w,
                   v2.x,v2.y,v2.z,v2.w, v3.x,v3.y,v3.z,v3.w};
    float mx = v[0];
#pragma unroll
    for (int i = 1; i < 16; i++) mx = fmaxf(mx, v[i]);
    float s = 0.f;
#pragma unroll
    for (int i = 0; i < 16; i++) { v[i] = __expf(0.25f * (v[i] - mx)); s += v[i]; }
    float inv = 1.f / s;
#pragma unroll
    for (int i = 0; i < 16; i++) v[i] *= inv;
    float4* dst = (float4*)(g_key + (size_t)r * 16);
    dst[0] = make_float4(v[0],v[1],v[2],v[3]);
    dst[1] = make_float4(v[4],v[5],v[6],v[7]);
    dst[2] = make_float4(v[8],v[9],v[10],v[11]);
    dst[3] = make_float4(v[12],v[13],v[14],v[15]);
}

__global__ void k_zero_kv() {
    int i = blockIdx.x * 256 + threadIdx.x;
    ((float4*)g_kv)[i] = make_float4(0.f, 0.f, 0.f, 0.f);
}

// ---------------- staging: B-fragments frag[nt(16)][chunk(8)][lane(32)] = {Bh0,Bh1,Bl0,Bl1} ----------------
__device__ __forceinline__ void stage_x(const float* __restrict__ xb, int pc, int tid,
                                        uint4* frag,
                                        const float* __restrict__ xb_next, int pc_next) {
    for (int u = tid; u < 4096; u += NTHR) {
        int lane = u & 31, chunk = (u >> 5) & 7, nt = u >> 8;
        int g = lane >> 2, t = lane & 3;
        int p = nt * 8 + g;
        int k0 = chunk * 16 + 2 * t;
        float v0 = 0.f, v1 = 0.f, v2 = 0.f, v3 = 0.f;
        if (p < pc) {
            v0 = __ldg(xb + (size_t)k0 * NPOS + p);
            v1 = __ldg(xb + (size_t)(k0 + 1) * NPOS + p);
            v2 = __ldg(xb + (size_t)(k0 + 8) * NPOS + p);
            v3 = __ldg(xb + (size_t)(k0 + 9) * NPOS + p);
        }
        uint4 r;
        r.x = packbf(v0, v1);
        r.y = packbf(v2, v3);
        r.z = packbf(v0 - rbf(v0), v1 - rbf(v1));
        r.w = packbf(v2 - rbf(v2), v3 - rbf(v3));
        frag[u] = r;
    }
    // prefetch next tile's x into L2 (128 rows x 4 lines)
    if (xb_next) {
        int c = tid >> 2, lo = (tid & 3) * 32;
        if (lo < pc_next) {
            const float* a = xb_next + (size_t)c * NPOS + lo;
            asm volatile("prefetch.global.L2 [%0];" :: "l"(a));
        }
    }
}
__device__ __forceinline__ void stage_o(const float* __restrict__ ob, int pc, int tid,
                                        uint4* frag) {
    const float2* o2 = (const float2*)ob;
    for (int u = tid; u < 4096; u += NTHR) {
        int lane = u & 31, chunk = (u >> 5) & 7, nt = u >> 8;
        int g = lane >> 2, t = lane & 3;
        int p = nt * 8 + g;
        float2 rA = make_float2(0.f, 0.f), rB = make_float2(0.f, 0.f);
        if (p < pc) {
            rA = __ldg(o2 + (size_t)p * 64 + chunk * 8 + t);
            rB = __ldg(o2 + (size_t)p * 64 + chunk * 8 + t + 4);
        }
        uint4 r;
        r.x = packbf(rA.x, rA.y);
        r.y = packbf(rB.x, rB.y);
        r.z = packbf(rA.x - rbf(rA.x), rA.y - rbf(rA.y));
        r.w = packbf(rB.x - rbf(rB.x), rB.y - rbf(rB.y));
        frag[u] = r;
    }
}

// load A-frags for weight w, strip (16 rows) from GLOBAL
__device__ __forceinline__ void load_afrag(int w, int strip, int lane,
                                           uint32_t aH[8][4], uint32_t aL[8][4]) {
    const uint4* PH = g_WFH + w*2048 + strip*256 + lane;
    const uint4* PL = g_WFL + w*2048 + strip*256 + lane;
#pragma unroll
    for (int ch = 0; ch < 8; ch++) {
        uint4 h = __ldg(PH + ch*32);
        uint4 l = __ldg(PL + ch*32);
        aH[ch][0] = h.x; aH[ch][1] = h.y; aH[ch][2] = h.z; aH[ch][3] = h.w;
        aL[ch][0] = l.x; aL[ch][1] = l.y; aL[ch][2] = l.z; aL[ch][3] = l.w;
    }
}

// 2-ntile GEMM (one weight), 3-term bf16 split (for kernelB2)
__device__ __forceinline__ void gemm_pair(const uint4* frag, int nt0, int lane,
                                          const uint32_t aH[8][4], const uint32_t aL[8][4],
                                          float d[2][4]) {
#pragma unroll
    for (int j = 0; j < 2; j++)
#pragma unroll
        for (int i = 0; i < 4; i++) d[j][i] = 0.f;
    const uint4* f0 = frag + nt0*256 + lane;
    const uint4* f1 = f0 + 256;
#pragma unroll
    for (int ch = 0; ch < 8; ch++) {
        uint4 B0 = f0[ch*32];
        uint4 B1 = f1[ch*32];
        mma16(d[0], aH[ch], B0.x, B0.y);
        mma16(d[1], aH[ch], B1.x, B1.y);
        mma16(d[0], aL[ch], B0.x, B0.y);
        mma16(d[1], aL[ch], B1.x, B1.y);
        mma16(d[0], aH[ch], B0.z, B0.w);
        mma16(d[1], aH[ch], B1.z, B1.w);
    }
}

// =======================================================================
// kernelQV: fused Q+V mainloop, shared B loads. 512 thr = 8 strips x 2 N-halves.
// smem: frag 64KB + Wq/Wv A-frags 128KB = 192KB
// =======================================================================
#define SMEM_QV_BYTES (12288 * 16)
__global__ void __launch_bounds__(NTHR, 1)
kernelQV(const float* __restrict__ x, const float* __restrict__ bq,
         const float* __restrict__ bv) {
    extern __shared__ uint4 sm[];
    uint4* frag = sm;              // 4096
    uint4* sWqH = sm + 4096;       // 2048
    uint4* sWqL = sm + 6144;
    uint4* sWvH = sm + 8192;
    uint4* sWvL = sm + 10240;

    int tid = threadIdx.x, wid = tid >> 5, lane = tid & 31;
    int mg = wid & 7, nh = wid >> 3;
    int g = lane >> 2, t = lane & 3;
    int ntbase = nh * 8;
    int ch0 = mg * 16 + g;

    for (int i = tid; i < 2048; i += NTHR) {
        sWqH[i] = g_WFH[i];        sWqL[i] = g_WFL[i];
        sWvH[i] = g_WFH[2048 + i]; sWvL[i] = g_WFL[2048 + i];
    }

    float bqlo = __ldg(bq + ch0), bqhi = __ldg(bq + ch0 + 8);
    float bvlo = __ldg(bv + ch0), bvhi = __ldg(bv + ch0 + 8);
    __syncthreads();

    for (int tt = blockIdx.x; tt < NTILES; tt += gridDim.x) {
        int b = tt / NT, p0 = (tt % NT) * TP;
        int pc = min(TP, NPOS - p0);

        int tn = tt + gridDim.x;
        const float* xb_next = 0; int pc_next = 0;
        if (tn < NTILES) {
            int bn = tn / NT, p0n = (tn % NT) * TP;
            xb_next = x + ((size_t)bn * CC) * NPOS + p0n;
            pc_next = min(TP, NPOS - p0n);
        }
        stage_x(x + ((size_t)b * CC) * NPOS + p0, pc, tid, frag, xb_next, pc_next);
        __syncthreads();

        // ---- fused mainloop: one B pass feeds both Q and V accumulators ----
        float dq[4][2][4], dv[4][2][4];
#pragma unroll
        for (int np = 0; np < 4; np++)
#pragma unroll
            for (int j = 0; j < 2; j++)
#pragma unroll
                for (int i = 0; i < 4; i++) { dq[np][j][i] = 0.f; dv[np][j][i] = 0.f; }

        const uint4* fbase = frag + ntbase*256 + lane;
        const uint4* wbase = sWqH;  // index helper below
        (void)wbase;
#pragma unroll 1
        for (int ch = 0; ch < 8; ch++) {
            int aidx = mg*256 + ch*32 + lane;
            uint4 qh = sWqH[aidx], ql = sWqL[aidx];
            uint4 vh = sWvH[aidx], vl = sWvL[aidx];
            uint32_t AQH[4] = {qh.x, qh.y, qh.z, qh.w};
            uint32_t AQL[4] = {ql.x, ql.y, ql.z, ql.w};
            uint32_t AVH[4] = {vh.x, vh.y, vh.z, vh.w};
            uint32_t AVL[4] = {vl.x, vl.y, vl.z, vl.w};
#pragma unroll
            for (int np = 0; np < 4; np++) {
                uint4 B0 = fbase[np*512 + ch*32];
                uint4 B1 = fbase[np*512 + 256 + ch*32];
                mma16(dq[np][0], AQH, B0.x, B0.y);
                mma16(dq[np][1], AQH, B1.x, B1.y);
                mma16(dv[np][0], AVH, B0.x, B0.y);
                mma16(dv[np][1], AVH, B1.x, B1.y);
                mma16(dq[np][0], AQL, B0.x, B0.y);
                mma16(dq[np][1], AQL, B1.x, B1.y);
                mma16(dv[np][0], AVL, B0.x, B0.y);
                mma16(dv[np][1], AVL, B1.x, B1.y);
                mma16(dq[np][0], AQH, B0.z, B0.w);
                mma16(dq[np][1], AQH, B1.z, B1.w);
                mma16(dv[np][0], AVH, B0.z, B0.w);
                mma16(dv[np][1], AVH, B1.z, B1.w);
            }
        }

        // ---- Q epilogue: bias + relu + softmax + store ----
        float* qb = g_q + ((size_t)b * NPOS + p0) * CC;
#pragma unroll
        for (int np = 0; np < 4; np++) {
#pragma unroll
            for (int j = 0; j < 2; j++) {
                int c0 = (ntbase + np*2 + j) * 8 + 2 * t;
                float v0 = fmaxf(dq[np][j][0] + bqlo, 0.f);
                float v1 = fmaxf(dq[np][j][1] + bqlo, 0.f);
                float v2 = fmaxf(dq[np][j][2] + bqhi, 0.f);
                float v3 = fmaxf(dq[np][j][3] + bqhi, 0.f);
                float me = fmaxf(v0, v2), mo = fmaxf(v1, v3);
#pragma unroll
                for (int o = 4; o < 32; o <<= 1) {
                    me = fmaxf(me, __shfl_xor_sync(0xffffffffu, me, o));
                    mo = fmaxf(mo, __shfl_xor_sync(0xffffffffu, mo, o));
                }
                float e0 = __expf(0.25f*(v0 - me)), e2 = __expf(0.25f*(v2 - me));
                float e1 = __expf(0.25f*(v1 - mo)), e3 = __expf(0.25f*(v3 - mo));
                float se = e0 + e2, so = e1 + e3;
#pragma unroll
                for (int o = 4; o < 32; o <<= 1) {
                    se += __shfl_xor_sync(0xffffffffu, se, o);
                    so += __shfl_xor_sync(0xffffffffu, so, o);
                }
                float ie = 1.f / se, io = 1.f / so;
                if (c0 < pc) {
                    qb[(size_t)c0 * CC + ch0]     = e0 * ie;
                    qb[(size_t)c0 * CC + ch0 + 8] = e2 * ie;
                }
                if (c0 + 1 < pc) {
                    qb[(size_t)(c0+1) * CC + ch0]     = e1 * io;
                    qb[(size_t)(c0+1) * CC + ch0 + 8] = e3 * io;
                }
            }
        }

        // ---- V epilogue: bias + relu + store ----
        float* vb = g_v + ((size_t)b * NPOS + p0) * CC;
#pragma unroll
        for (int np = 0; np < 4; np++) {
#pragma unroll
            for (int j = 0; j < 2; j++) {
                int c0 = (ntbase + np*2 + j) * 8 + 2 * t;
                if (c0 < pc) {
                    vb[(size_t)c0 * CC + ch0]     = fmaxf(dv[np][j][0] + bvlo, 0.f);
                    vb[(size_t)c0 * CC + ch0 + 8] = fmaxf(dv[np][j][2] + bvhi, 0.f);
                }
                if (c0 + 1 < pc) {
                    vb[(size_t)(c0+1) * CC + ch0]     = fmaxf(dv[np][j][1] + bvlo, 0.f);
                    vb[(size_t)(c0+1) * CC + ch0 + 8] = fmaxf(dv[np][j][3] + bvhi, 0.f);
                }
            }
        }
        __syncthreads();
    }
}

// =======================================================================
// k_kv: kv[b,l,h,x,y] += sum_n key[h,l,n,x] * v[b, n*12+l, h*16+y]
// =======================================================================
#define NCHUNK 250
__global__ void __launch_bounds__(256, 4)
k_kv() {
    int nc = blockIdx.x, l = blockIdx.y, b = blockIdx.z;
    int tid = threadIdx.x, wid = tid >> 5, lane = tid & 31;
    int h = wid;
    int xk = lane & 15, yb = (lane >> 4) * 8;
    int n0 = nc * NCHUNK;

    const float* keyh = g_key + (((size_t)h * LLL + l) * NNN) * DKK;
    const float* vbase = g_v + ((size_t)b * NPOS + l) * CC + h * 16 + yb;

    float acc[8];
#pragma unroll
    for (int j = 0; j < 8; j++) acc[j] = 0.f;

#pragma unroll 2
    for (int n = n0; n < n0 + NCHUNK; n++) {
        float kx = __ldg(keyh + (size_t)n * DKK + xk);
        const float4* vp = (const float4*)(vbase + (size_t)n * 12 * CC);
        float4 vA = __ldg(vp), vB = __ldg(vp + 1);
        acc[0] = fmaf(kx, vA.x, acc[0]); acc[1] = fmaf(kx, vA.y, acc[1]);
        acc[2] = fmaf(kx, vA.z, acc[2]); acc[3] = fmaf(kx, vA.w, acc[3]);
        acc[4] = fmaf(kx, vB.x, acc[4]); acc[5] = fmaf(kx, vB.y, acc[5]);
        acc[6] = fmaf(kx, vB.z, acc[6]); acc[7] = fmaf(kx, vB.w, acc[7]);
    }
    float* kvp = g_kv + ((((size_t)b * LLL + l) * HEAD + h) * DKK + xk) * DKK + yb;
#pragma unroll
    for (int j = 0; j < 8; j++) atomicAdd(kvp + j, acc[j]);
}

// =======================================================================
// kernelB1: o[b,p,:] = q[b,p,:] @ kv[b,l(p)]
// warp-per-position, lane = 4 output channels; kv column block in regs.
// =======================================================================
#define B1_NPB 250
__global__ void __launch_bounds__(256, 2)
kernelB1() {
    int nc = blockIdx.x, l = blockIdx.y, b = blockIdx.z;
    int tid = threadIdx.x, wid = tid >> 5, lane = tid & 31;
    int h = lane >> 2, yq = lane & 3;   // lane -> channels h*16 + yq*4 .. +3

    // kvr[y][x] = kv[b][l][h][x][yq*4+y]
    const float* kvb = g_kv + (((size_t)b * LLL + l) * HEAD + h) * 256;
    float kvr[4][16];
#pragma unroll
    for (int xx = 0; xx < 16; xx++) {
        float4 kr = __ldg((const float4*)(kvb + xx * 16 + yq * 4));
        kvr[0][xx] = kr.x; kvr[1][xx] = kr.y; kvr[2][xx] = kr.z; kvr[3][xx] = kr.w;
    }

    int n0 = nc * B1_NPB;
    for (int i = wid; i < B1_NPB; i += 8) {
        int n = n0 + i;
        size_t P = (size_t)b * NPOS + (size_t)n * 12 + l;
        const float4* qr = (const float4*)(g_q + P * CC);
        // all 16 q values of head h (quad-broadcast loads)
        float4 q0 = __ldg(qr + h * 4 + 0);
        float4 q1 = __ldg(qr + h * 4 + 1);
        float4 q2 = __ldg(qr + h * 4 + 2);
        float4 q3 = __ldg(qr + h * 4 + 3);
        float o0 = 0.f, o1 = 0.f, o2 = 0.f, o3 = 0.f;
#define B1ACC(qq, xb_) \
        o0 = fmaf(qq.x, kvr[0][xb_+0], o0); o1 = fmaf(qq.x, kvr[1][xb_+0], o1); \
        o2 = fmaf(qq.x, kvr[2][xb_+0], o2); o3 = fmaf(qq.x, kvr[3][xb_+0], o3); \
        o0 = fmaf(qq.y, kvr[0][xb_+1], o0); o1 = fmaf(qq.y, kvr[1][xb_+1], o1); \
        o2 = fmaf(qq.y, kvr[2][xb_+1], o2); o3 = fmaf(qq.y, kvr[3][xb_+1], o3); \
        o0 = fmaf(qq.z, kvr[0][xb_+2], o0); o1 = fmaf(qq.z, kvr[1][xb_+2], o1); \
        o2 = fmaf(qq.z, kvr[2][xb_+2], o2); o3 = fmaf(qq.z, kvr[3][xb_+2], o3); \
        o0 = fmaf(qq.w, kvr[0][xb_+3], o0); o1 = fmaf(qq.w, kvr[1][xb_+3], o1); \
        o2 = fmaf(qq.w, kvr[2][xb_+3], o2); o3 = fmaf(qq.w, kvr[3][xb_+3], o3);
        B1ACC(q0, 0) B1ACC(q1, 4) B1ACC(q2, 8) B1ACC(q3, 12)
#undef B1ACC
        ((float4*)(g_o + P * CC))[lane] = make_float4(o0, o1, o2, o3);
    }
}

// =======================================================================
// kernelB2: out = relu(Wc o + bc) -> out[b][c][p], 512 threads
// =======================================================================
#define SMEM_B2_BYTES (4096*16)
__global__ void __launch_bounds__(NTHR, 1)
kernelB2(const float* __restrict__ bc, float* __restrict__ out) {
    extern __shared__ uint4 frag[];

    int tid = threadIdx.x, wid = tid >> 5, lane = tid & 31;
    int mg = wid & 7, nh = wid >> 3;
    int g = lane >> 2, t = lane & 3;
    int ntbase = nh * 8;
    int ch0 = mg * 16 + g;

    uint32_t aH[8][4], aL[8][4];
    load_afrag(2, mg, lane, aH, aL);
    float bclo = __ldg(bc + ch0), bchi = __ldg(bc + ch0 + 8);

    for (int tt = blockIdx.x; tt < NTILES; tt += gridDim.x) {
        int b = tt / NT, p0 = (tt % NT) * TP;
        int pc = min(TP, NPOS - p0);

        stage_o(g_o + ((size_t)b * NPOS + p0) * CC, pc, tid, frag);
        __syncthreads();

        float* ob = out + (size_t)b * CC * NPOS + p0;
#pragma unroll 1
        for (int ntp = 0; ntp < 4; ntp++) {
            int nt0 = ntbase + ntp * 2;
            float d[2][4];
            gemm_pair(frag, nt0, lane, aH, aL, d);
#pragma unroll
            for (int j = 0; j < 2; j++) {
                int c0 = (nt0 + j) * 8 + 2 * t;
                float w0 = fmaxf(d[j][0] + bclo, 0.f);
                float w1 = fmaxf(d[j][1] + bclo, 0.f);
                float w2 = fmaxf(d[j][2] + bchi, 0.f);
                float w3 = fmaxf(d[j][3] + bchi, 0.f);
                if (c0 + 1 < pc) {
                    *(float2*)(ob + (size_t)ch0 * NPOS + c0)       = make_float2(w0, w1);
                    *(float2*)(ob + (size_t)(ch0 + 8) * NPOS + c0) = make_float2(w2, w3);
                } else if (c0 < pc) {
                    ob[(size_t)ch0 * NPOS + c0]       = w0;
                    ob[(size_t)(ch0 + 8) * NPOS + c0] = w2;
                }
            }
        }
        __syncthreads();
    }
}

// ---------------- launch ----------------
extern "C" void kernel_launch(void* const* d_in, const int* in_sizes, int n_in,
                              void* d_out, int out_size) {
    (void)in_sizes; (void)n_in; (void)out_size;
    const float* x      = (const float*)d_in[0];
    const float* Wq     = (const float*)d_in[1];
    const float* bq     = (const float*)d_in[2];
    const float* Wv     = (const float*)d_in[3];
    const float* bv     = (const float*)d_in[4];
    const float* Wc     = (const float*)d_in[5];
    const float* bc     = (const float*)d_in[6];
    const float* s_bank = (const float*)d_in[7];
    float* out = (float*)d_out;

    cudaFuncSetAttribute(kernelQV, cudaFuncAttributeMaxDynamicSharedMemorySize, SMEM_QV_BYTES);
    cudaFuncSetAttribute(kernelB2, cudaFuncAttributeMaxDynamicSharedMemorySize, SMEM_B2_BYTES);

    k_prep_w<<<3, 256>>>(Wq, Wv, Wc);
    k_key<<<(HEAD*LLL*NNN + 255) / 256, 256>>>(s_bank);
    k_zero_kv<<<(BB*LLL*HEAD*DKK*DKK/4) / 256, 256>>>();
    kernelQV<<<GRID_PERS, NTHR, SMEM_QV_BYTES>>>(x, bq, bv);
    k_kv<<<dim3(NNN/NCHUNK, LLL, BB), 256>>>();
    kernelB1<<<dim3(NNN/B1_NPB, LLL, BB), 256>>>();
    kernelB2<<<GRID_PERS, NTHR, SMEM_B2_BYTES>>>(bc, out);
}